// round 5
// baseline (speedup 1.0000x reference)
#include <cuda_runtime.h>
#include <cstdint>

#define Vv 50257
#define Hd 1024
#define Sd 2048
#define TWO_H 2048
#define VS (Vv + Sd)          // 52305
#define POS_H1 VS
#define POS_C1 (VS + Hd)

// ---------------- scratch ----------------
__device__ float g_att[Sd];
__device__ float g_attnw[Sd];
__device__ float g_rho[Sd];
__device__ float g_ctx[TWO_H];
__device__ float g_sel0[TWO_H];
__device__ float g_lstm_in[3 * Hd];
__device__ float g_gates[4 * Hd];
__device__ float g_h1[Hd];
__device__ float g_pmax[64];
__device__ float g_psum[64];

// ---------------- helpers ----------------
__device__ __forceinline__ float wredsum(float v) {
#pragma unroll
    for (int o = 16; o; o >>= 1) v += __shfl_xor_sync(0xffffffffu, v, o);
    return v;
}

__device__ __forceinline__ float blockSum(float v) {
    __shared__ float red[32];
    int lane = threadIdx.x & 31, w = threadIdx.x >> 5;
    int nw = (blockDim.x + 31) >> 5;
    v = wredsum(v);
    if (lane == 0) red[w] = v;
    __syncthreads();
    if (threadIdx.x == 0) {
        float s = 0.f;
        for (int i = 0; i < nw; i++) s += red[i];
        red[0] = s;
    }
    __syncthreads();
    float r = red[0];
    __syncthreads();
    return r;
}

__device__ __forceinline__ float blockMax(float v) {
    __shared__ float red[32];
    int lane = threadIdx.x & 31, w = threadIdx.x >> 5;
    int nw = (blockDim.x + 31) >> 5;
#pragma unroll
    for (int o = 16; o; o >>= 1) v = fmaxf(v, __shfl_xor_sync(0xffffffffu, v, o));
    if (lane == 0) red[w] = v;
    __syncthreads();
    if (threadIdx.x == 0) {
        float s = -3.4e38f;
        for (int i = 0; i < nw; i++) s = fmaxf(s, red[i]);
        red[0] = s;
    }
    __syncthreads();
    float r = red[0];
    __syncthreads();
    return r;
}

__device__ __forceinline__ unsigned long long ffma2(unsigned long long a,
                                                    unsigned long long b,
                                                    unsigned long long c) {
    unsigned long long d;
    asm("fma.rn.f32x2 %0, %1, %2, %3;" : "=l"(d) : "l"(a), "l"(b), "l"(c));
    return d;
}
__device__ __forceinline__ unsigned long long pk2(float x, float y) {
    unsigned long long u;
    asm("mov.b64 %0, {%1,%2};" : "=l"(u) : "f"(x), "f"(y));
    return u;
}
__device__ __forceinline__ float2 upk2(unsigned long long u) {
    float2 f;
    asm("mov.b64 {%0,%1}, %2;" : "=f"(f.x), "=f"(f.y) : "l"(u));
    return f;
}
__device__ __forceinline__ float dot4(float4 a, float4 b) {
    return a.x * b.x + a.y * b.y + a.z * b.z + a.w * b.w;
}
__device__ __forceinline__ float sigf(float x) { return 1.f / (1.f + expf(-x)); }

// ============ K_P1: blocks 0-127 att | 128-383 gates_early | 384-391 zero ======
// gates_early: g_gates[r] = W_ih[r, 0:1024] . xe + W_hh[r,:] . h0   (partial)
__global__ void k_p1(const float* __restrict__ x, const float* __restrict__ h0,
                     const float* __restrict__ attn_W, const float* __restrict__ attn_b,
                     const float* __restrict__ W_ih, const float* __restrict__ W_hh,
                     float* __restrict__ out) {
    int b = blockIdx.x;
    if (b >= 384) {  // zero ctx/sel0 + out[Vv..Vv+Sd)
        int i = (b - 384) * 256 + threadIdx.x;  // 0..2047
        g_ctx[i] = 0.f;
        g_sel0[i] = 0.f;
        out[Vv + i] = 0.f;
        return;
    }
    __shared__ float z[TWO_H];  // [xe | h0]
    int t = threadIdx.x, lane = t & 31, warp = t >> 5;
    for (int i = t; i < Hd; i += 256) { z[i] = x[i]; z[Hd + i] = h0[i]; }
    __syncthreads();
    const float4* Z = (const float4*)z;

    if (b < 128) {  // ---- att logits: rows b*16 + warp*2 (+1) over [xe,h0] ----
        int r0 = b * 16 + warp * 2, r1 = r0 + 1;
        const float4* W0 = (const float4*)(attn_W + (size_t)r0 * TWO_H);
        const float4* W1 = (const float4*)(attn_W + (size_t)r1 * TWO_H);
        float s0 = 0.f, s1 = 0.f;
#pragma unroll
        for (int half = 0; half < 2; half++) {
            float4 a[8], bb[8];
#pragma unroll
            for (int j = 0; j < 8; j++) a[j] = W0[lane + (half * 8 + j) * 32];
#pragma unroll
            for (int j = 0; j < 8; j++) bb[j] = W1[lane + (half * 8 + j) * 32];
#pragma unroll
            for (int j = 0; j < 8; j++) {
                float4 zz = Z[lane + (half * 8 + j) * 32];
                s0 += dot4(a[j], zz);
                s1 += dot4(bb[j], zz);
            }
        }
        s0 = wredsum(s0);
        s1 = wredsum(s1);
        if (lane == 0) {
            g_att[r0] = s0 + attn_b[r0];
            g_att[r1] = s1 + attn_b[r1];
        }
    } else {  // ---- gates_early: rows (b-128)*16 + warp*2 of 4096 ----
        int r0 = (b - 128) * 16 + warp * 2, r1 = r0 + 1;
        const float4* Wx0 = (const float4*)(W_ih + (size_t)r0 * (3 * Hd));  // xe cols
        const float4* Wx1 = (const float4*)(W_ih + (size_t)r1 * (3 * Hd));
        const float4* Wh0 = (const float4*)(W_hh + (size_t)r0 * Hd);
        const float4* Wh1 = (const float4*)(W_hh + (size_t)r1 * Hd);
        float s0 = 0.f, s1 = 0.f;
        {
            float4 a[8], bb[8];
#pragma unroll
            for (int j = 0; j < 8; j++) a[j] = Wx0[lane + j * 32];
#pragma unroll
            for (int j = 0; j < 8; j++) bb[j] = Wx1[lane + j * 32];
#pragma unroll
            for (int j = 0; j < 8; j++) {
                float4 zz = Z[lane + j * 32];  // xe
                s0 += dot4(a[j], zz);
                s1 += dot4(bb[j], zz);
            }
        }
        {
            float4 a[8], bb[8];
#pragma unroll
            for (int j = 0; j < 8; j++) a[j] = Wh0[lane + j * 32];
#pragma unroll
            for (int j = 0; j < 8; j++) bb[j] = Wh1[lane + j * 32];
#pragma unroll
            for (int j = 0; j < 8; j++) {
                float4 zz = Z[256 + lane + j * 32];  // h0
                s0 += dot4(a[j], zz);
                s1 += dot4(bb[j], zz);
            }
        }
        s0 = wredsum(s0);
        s1 = wredsum(s1);
        if (lane == 0) { g_gates[r0] = s0; g_gates[r1] = s1; }
    }
}

// ---------------- K2: softmax(att), rho, copy xe ----------------
__global__ void k_soft_rho(const int* __restrict__ sentence,
                           const float* __restrict__ prev_probs,
                           const int* __restrict__ prev_word,
                           const float* __restrict__ x) {
    int t = threadIdx.x;  // 1024
    g_lstm_in[t] = x[t];
    float a0 = g_att[t], a1 = g_att[t + 1024];
    float M = blockMax(fmaxf(a0, a1));
    float e0 = expf(a0 - M), e1 = expf(a1 - M);
    float Ssum = blockSum(e0 + e1);
    float inv = 1.f / Ssum;
    g_attnw[t] = e0 * inv;
    g_attnw[t + 1024] = e1 * inv;

    int pw = prev_word[0];
    float r0 = (sentence[t] == pw) ? prev_probs[Vv + t] : 0.f;
    float r1 = (sentence[t + 1024] == pw) ? prev_probs[Vv + t + 1024] : 0.f;
    float Rs = blockSum(r0 + r1);
    float rin = 1.f / (Rs + 1e-9f);
    g_rho[t] = r0 * rin;
    g_rho[t + 1024] = r1 * rin;
}

// ---------------- K3: ctx / sel0 ----------------
__global__ void k_ctx(const float* __restrict__ enc) {
    __shared__ float aw[64], rh[64];
    int t = threadIdx.x;
    int cb = blockIdx.x & 7;
    int sc = blockIdx.x >> 3;
    int col = cb * 256 + t;
    int s0 = sc * 64;
    if (t < 64) { aw[t] = g_attnw[s0 + t]; rh[t] = g_rho[s0 + t]; }
    __syncthreads();
    float ac = 0.f, as = 0.f;
#pragma unroll 16
    for (int i = 0; i < 64; i++) {
        float e = enc[(size_t)(s0 + i) * TWO_H + col];
        ac += aw[i] * e;
        as += rh[i] * e;
    }
    atomicAdd(&g_ctx[col], ac);
    atomicAdd(&g_sel0[col], as);
}

// ---------------- K4: projections ----------------
__global__ void k_proj(const float* __restrict__ comb_W, const float* __restrict__ comb_b,
                       const float* __restrict__ Ws_W, const float* __restrict__ Ws_b) {
    __shared__ float z[TWO_H];
    int t = threadIdx.x, lane = t & 31, warp = t >> 5;
    bool sel = blockIdx.x < 64;
    const float* src = sel ? g_sel0 : g_ctx;
    for (int i = t; i < TWO_H; i += 256) z[i] = src[i];
    __syncthreads();
    int r0 = (blockIdx.x & 63) * 16 + warp * 2, r1 = r0 + 1;
    const float* W = sel ? Ws_W : comb_W;
    const float4* W0 = (const float4*)(W + (size_t)r0 * TWO_H);
    const float4* W1 = (const float4*)(W + (size_t)r1 * TWO_H);
    const float4* Z = (const float4*)z;
    float s0 = 0.f, s1 = 0.f;
#pragma unroll
    for (int half = 0; half < 2; half++) {
        float4 a[8], b[8];
#pragma unroll
        for (int j = 0; j < 8; j++) a[j] = W0[lane + (half * 8 + j) * 32];
#pragma unroll
        for (int j = 0; j < 8; j++) b[j] = W1[lane + (half * 8 + j) * 32];
#pragma unroll
        for (int j = 0; j < 8; j++) {
            float4 zz = Z[lane + (half * 8 + j) * 32];
            s0 += dot4(a[j], zz);
            s1 += dot4(b[j], zz);
        }
    }
    s0 = wredsum(s0);
    s1 = wredsum(s1);
    if (lane == 0) {
        if (sel) { g_lstm_in[Hd + r0] = s0 + Ws_b[r0]; g_lstm_in[Hd + r1] = s1 + Ws_b[r1]; }
        else     { g_lstm_in[2 * Hd + r0] = s0 + comb_b[r0]; g_lstm_in[2 * Hd + r1] = s1 + comb_b[r1]; }
    }
}

// ---------------- K5: gates_late: += W_ih[:,1024:3072] . lstm_in[1024:3072] ----
__global__ void k_gates2(const float* __restrict__ W_ih) {
    __shared__ float z[TWO_H];
    int t = threadIdx.x, lane = t & 31, warp = t >> 5;
    for (int i = t; i < TWO_H; i += 256) z[i] = g_lstm_in[Hd + i];
    __syncthreads();
    int r0 = blockIdx.x * 16 + warp * 2, r1 = r0 + 1;  // 0..4095
    const float4* W0 = (const float4*)(W_ih + (size_t)r0 * (3 * Hd) + Hd);
    const float4* W1 = (const float4*)(W_ih + (size_t)r1 * (3 * Hd) + Hd);
    const float4* Z = (const float4*)z;
    float s0 = 0.f, s1 = 0.f;
#pragma unroll
    for (int half = 0; half < 2; half++) {
        float4 a[8], b[8];
#pragma unroll
        for (int j = 0; j < 8; j++) a[j] = W0[lane + (half * 8 + j) * 32];
#pragma unroll
        for (int j = 0; j < 8; j++) b[j] = W1[lane + (half * 8 + j) * 32];
#pragma unroll
        for (int j = 0; j < 8; j++) {
            float4 zz = Z[lane + (half * 8 + j) * 32];
            s0 += dot4(a[j], zz);
            s1 += dot4(b[j], zz);
        }
    }
    s0 = wredsum(s0);
    s1 = wredsum(s1);
    if (lane == 0) {
        g_gates[r0] += s0;
        g_gates[r1] += s1;
    }
}

// ---------------- K6: LSTM cell ----------------
__global__ void k_cell(const float* __restrict__ b_ih, const float* __restrict__ b_hh,
                       const float* __restrict__ c0, float* __restrict__ out) {
    int k = blockIdx.x * 256 + threadIdx.x;
    float iv = g_gates[k]          + b_ih[k]          + b_hh[k];
    float fv = g_gates[k + Hd]     + b_ih[k + Hd]     + b_hh[k + Hd];
    float gv = g_gates[k + 2 * Hd] + b_ih[k + 2 * Hd] + b_hh[k + 2 * Hd];
    float ov = g_gates[k + 3 * Hd] + b_ih[k + 3 * Hd] + b_hh[k + 3 * Hd];
    float c1 = sigf(fv) * c0[k] + sigf(iv) * tanhf(gv);
    float h1 = sigf(ov) * tanhf(c1);
    g_h1[k] = h1;
    out[POS_H1 + k] = h1;
    out[POS_C1 + k] = c1;
}

// ---------------- K_BIG: scorec (blocks 0..127, FFMA2) + scoreg (128+) --------
// smem layout (dynamic): hs[128] @0, bs[128] @512, As2 u64[32][130] @1024,
//                        Bs float[32][132] @34304 ; total 51200 B
#define SC_NBLK 128
#define OFF_HS  0
#define OFF_BS  512
#define OFF_A2  1024
#define A2_LD   130
#define OFF_B   34304
#define B_LD    132
#define SMEM_BIG 51200

__global__ void __launch_bounds__(256, 2) k_big(
    const float* __restrict__ enc, const float* __restrict__ Wc_W,
    const float* __restrict__ Wc_b, const float* __restrict__ Wo_W,
    const float* __restrict__ Wo_b, float* __restrict__ out) {
    extern __shared__ char smem[];
    int t = threadIdx.x, lane = t & 31, wid = t >> 5;

    if (blockIdx.x >= SC_NBLK) {
        // ===== scoreg: out[r] = Wo_W[r,:] . h1 + Wo_b[r] =====
        int warpg = (blockIdx.x - SC_NBLK) * 8 + wid;
        int r0 = warpg * 2, r1 = r0 + 1;
        if (r0 >= Vv) return;
        float4 hf[8];
        const float4* H4 = (const float4*)g_h1;
#pragma unroll
        for (int j = 0; j < 8; j++) hf[j] = H4[lane + j * 32];
        const float4* W0 = (const float4*)(Wo_W + (size_t)r0 * Hd);
        const float4* W1 = (const float4*)(Wo_W + (size_t)r1 * Hd);
        bool has1 = (r1 < Vv);
        float4 a[8], b[8];
#pragma unroll
        for (int j = 0; j < 8; j++) a[j] = W0[lane + j * 32];
        if (has1) {
#pragma unroll
            for (int j = 0; j < 8; j++) b[j] = W1[lane + j * 32];
        }
        float s0 = 0.f, s1 = 0.f;
#pragma unroll
        for (int j = 0; j < 8; j++) s0 += dot4(a[j], hf[j]);
        if (has1) {
#pragma unroll
            for (int j = 0; j < 8; j++) s1 += dot4(b[j], hf[j]);
        }
        s0 = wredsum(s0);
        s1 = wredsum(s1);
        if (lane == 0) {
            out[r0] = s0 + Wo_b[r0];
            if (has1) out[r1] = s1 + Wo_b[r1];
        }
        return;
    }

    // ===== scorec: 128x128 tile of M = enc @ Wc^T; out += tanh(M+b) . h1 =====
    float* hs = (float*)(smem + OFF_HS);
    float* bs = (float*)(smem + OFF_BS);
    unsigned long long* As2 = (unsigned long long*)(smem + OFF_A2);
    float* Bs = (float*)(smem + OFF_B);

    int s0 = (blockIdx.x & 15) * 128;   // 16 s-blocks
    int j0 = (blockIdx.x >> 4) * 128;   // 8 j-blocks
    int tx = t & 15, ty = t >> 4;
    int m0 = ty * 8, jj0 = tx * 8;

    if (t < 128) { hs[t] = g_h1[j0 + t]; bs[t] = Wc_b[j0 + t]; }

    const float4* A4 = (const float4*)enc;   // row stride 512 float4
    const float4* B4 = (const float4*)Wc_W;

    // prefetch chunk 0
    float4 ra[4], rb[4];
#pragma unroll
    for (int p = 0; p < 4; p++) {
        int f = t + p * 256;
        int row = f >> 3, kq = f & 7;   // row 0..127, kq 0..7
        ra[p] = A4[(size_t)(s0 + row) * 512 + kq];
        rb[p] = B4[(size_t)(j0 + row) * 512 + kq];
    }

    unsigned long long c[8][4] = {};
    for (int ch = 0; ch < 64; ch++) {   // K chunks of 32
        __syncthreads();
        // store chunk ch (transposed, A duplicated to f32x2)
#pragma unroll
        for (int p = 0; p < 4; p++) {
            int f = t + p * 256;
            int row = f >> 3, kq = f & 7;
            float4 va = ra[p], vb = rb[p];
            As2[(kq * 4 + 0) * A2_LD + row] = pk2(va.x, va.x);
            As2[(kq * 4 + 1) * A2_LD + row] = pk2(va.y, va.y);
            As2[(kq * 4 + 2) * A2_LD + row] = pk2(va.z, va.z);
            As2[(kq * 4 + 3) * A2_LD + row] = pk2(va.w, va.w);
            Bs[(kq * 4 + 0) * B_LD + row] = vb.x;
            Bs[(kq * 4 + 1) * B_LD + row] = vb.y;
            Bs[(kq * 4 + 2) * B_LD + row] = vb.z;
            Bs[(kq * 4 + 3) * B_LD + row] = vb.w;
        }
        // prefetch next chunk (overlaps with compute)
        if (ch < 63) {
            int kb = (ch + 1) * 8;
#pragma unroll
            for (int p = 0; p < 4; p++) {
                int f = t + p * 256;
                int row = f >> 3, kq = f & 7;
                ra[p] = A4[(size_t)(s0 + row) * 512 + kb + kq];
                rb[p] = B4[(size_t)(j0 + row) * 512 + kb + kq];
            }
        }
        __syncthreads();
#pragma unroll
        for (int kk = 0; kk < 32; kk++) {
            const ulonglong2* Ar = (const ulonglong2*)&As2[kk * A2_LD + m0];
            ulonglong2 a01 = Ar[0], a23 = Ar[1], a45 = Ar[2], a67 = Ar[3];
            const ulonglong2* Br = (const ulonglong2*)&Bs[kk * B_LD + jj0];
            ulonglong2 b01 = Br[0], b23 = Br[1];
            c[0][0] = ffma2(a01.x, b01.x, c[0][0]); c[0][1] = ffma2(a01.x, b01.y, c[0][1]);
            c[0][2] = ffma2(a01.x, b23.x, c[0][2]); c[0][3] = ffma2(a01.x, b23.y, c[0][3]);
            c[1][0] = ffma2(a01.y, b01.x, c[1][0]); c[1][1] = ffma2(a01.y, b01.y, c[1][1]);
            c[1][2] = ffma2(a01.y, b23.x, c[1][2]); c[1][3] = ffma2(a01.y, b23.y, c[1][3]);
            c[2][0] = ffma2(a23.x, b01.x, c[2][0]); c[2][1] = ffma2(a23.x, b01.y, c[2][1]);
            c[2][2] = ffma2(a23.x, b23.x, c[2][2]); c[2][3] = ffma2(a23.x, b23.y, c[2][3]);
            c[3][0] = ffma2(a23.y, b01.x, c[3][0]); c[3][1] = ffma2(a23.y, b01.y, c[3][1]);
            c[3][2] = ffma2(a23.y, b23.x, c[3][2]); c[3][3] = ffma2(a23.y, b23.y, c[3][3]);
            c[4][0] = ffma2(a45.x, b01.x, c[4][0]); c[4][1] = ffma2(a45.x, b01.y, c[4][1]);
            c[4][2] = ffma2(a45.x, b23.x, c[4][2]); c[4][3] = ffma2(a45.x, b23.y, c[4][3]);
            c[5][0] = ffma2(a45.y, b01.x, c[5][0]); c[5][1] = ffma2(a45.y, b01.y, c[5][1]);
            c[5][2] = ffma2(a45.y, b23.x, c[5][2]); c[5][3] = ffma2(a45.y, b23.y, c[5][3]);
            c[6][0] = ffma2(a67.x, b01.x, c[6][0]); c[6][1] = ffma2(a67.x, b01.y, c[6][1]);
            c[6][2] = ffma2(a67.x, b23.x, c[6][2]); c[6][3] = ffma2(a67.x, b23.y, c[6][3]);
            c[7][0] = ffma2(a67.y, b01.x, c[7][0]); c[7][1] = ffma2(a67.y, b01.y, c[7][1]);
            c[7][2] = ffma2(a67.y, b23.x, c[7][2]); c[7][3] = ffma2(a67.y, b23.y, c[7][3]);
        }
    }

    // epilogue: part[m] = sum_j tanh(c + bs[j]) * hs[j]; reduce over tx (16 lanes)
#pragma unroll
    for (int m = 0; m < 8; m++) {
        float part = 0.f;
#pragma unroll
        for (int jp = 0; jp < 4; jp++) {
            float2 f = upk2(c[m][jp]);
            int j = jj0 + jp * 2;
            part += tanhf(f.x + bs[j]) * hs[j];
            part += tanhf(f.y + bs[j + 1]) * hs[j + 1];
        }
#pragma unroll
        for (int o = 8; o; o >>= 1) part += __shfl_xor_sync(0xffffffffu, part, o);
        if ((lane & 15) == 0) atomicAdd(&out[Vv + s0 + m0 + m], part);
    }
}

// ---------------- final softmax over out[0:VS) ----------------
__global__ void k_pmax(const float* __restrict__ out) {
    float m = -3.4e38f;
    for (int i = blockIdx.x * 256 + threadIdx.x; i < VS; i += 64 * 256)
        m = fmaxf(m, out[i]);
    m = blockMax(m);
    if (threadIdx.x == 0) g_pmax[blockIdx.x] = m;
}

__global__ void k_expsum(float* __restrict__ out) {
    float m = -3.4e38f;
    for (int i = threadIdx.x; i < 64; i += 256) m = fmaxf(m, g_pmax[i]);
    float M = blockMax(m);
    float s = 0.f;
    for (int i = blockIdx.x * 256 + threadIdx.x; i < VS; i += 64 * 256) {
        float e = expf(out[i] - M);
        out[i] = e;
        s += e;
    }
    s = blockSum(s);
    if (threadIdx.x == 0) g_psum[blockIdx.x] = s;
}

__global__ void k_norm(float* __restrict__ out) {
    float s = 0.f;
    for (int i = threadIdx.x; i < 64; i += 256) s += g_psum[i];
    float tot = blockSum(s);
    float inv = 1.f / tot;
    for (int i = blockIdx.x * 256 + threadIdx.x; i < VS; i += 64 * 256)
        out[i] *= inv;
}

// ---------------- launch ----------------
extern "C" void kernel_launch(void* const* d_in, const int* in_sizes, int n_in,
                              void* d_out, int out_size) {
    const float* x          = (const float*)d_in[0];
    const float* enc        = (const float*)d_in[1];
    const int*   sentence   = (const int*)d_in[2];
    const float* prev_probs = (const float*)d_in[3];
    const float* h0         = (const float*)d_in[4];
    const float* c0         = (const float*)d_in[5];
    const float* attn_W     = (const float*)d_in[6];
    const float* attn_b     = (const float*)d_in[7];
    const float* comb_W     = (const float*)d_in[8];
    const float* comb_b     = (const float*)d_in[9];
    const float* Ws_W       = (const float*)d_in[10];
    const float* Ws_b       = (const float*)d_in[11];
    const float* Wo_W       = (const float*)d_in[12];
    const float* Wo_b       = (const float*)d_in[13];
    const float* Wc_W       = (const float*)d_in[14];
    const float* Wc_b       = (const float*)d_in[15];
    const float* W_ih       = (const float*)d_in[16];
    const float* W_hh       = (const float*)d_in[17];
    const float* b_ih       = (const float*)d_in[18];
    const float* b_hh       = (const float*)d_in[19];
    const int*   prev_word  = (const int*)d_in[20];
    float* out = (float*)d_out;

    static int smem_set = 0;
    if (!smem_set) {
        cudaFuncSetAttribute(k_big, cudaFuncAttributeMaxDynamicSharedMemorySize, SMEM_BIG);
        smem_set = 1;
    }

    k_p1<<<392, 256>>>(x, h0, attn_W, attn_b, W_ih, W_hh, out);
    k_soft_rho<<<1, 1024>>>(sentence, prev_probs, prev_word, x);
    k_ctx<<<256, 256>>>(enc);
    k_proj<<<128, 256>>>(comb_W, comb_b, Ws_W, Ws_b);
    k_gates2<<<256, 256>>>(W_ih);
    k_cell<<<4, 256>>>(b_ih, b_hh, c0, out);
    k_big<<<SC_NBLK + 3142, 256, SMEM_BIG>>>(enc, Wc_W, Wc_b, Wo_W, Wo_b, out);
    k_pmax<<<64, 256>>>(out);
    k_expsum<<<64, 256>>>(out);
    k_norm<<<64, 256>>>(out);
}

// round 8
// speedup vs baseline: 1.8755x; 1.8755x over previous
#include <cuda_runtime.h>
#include <cstdint>

#define Vv 50257
#define Hd 1024
#define Sd 2048
#define TWO_H 2048
#define VS (Vv + Sd)          // 52305
#define POS_H1 VS
#define POS_C1 (VS + Hd)

// ---------------- scratch ----------------
__device__ float g_att[Sd];
__device__ float g_attnw[Sd];
__device__ float g_rho[Sd];
__device__ float g_ctx[TWO_H];
__device__ float g_sel0[TWO_H];
__device__ float g_lstm_in[3 * Hd];
__device__ float g_gates[4 * Hd];
__device__ float g_h1[Hd];
__device__ float g_pmax[64];
__device__ float g_psum[64];

// ---------------- helpers ----------------
__device__ __forceinline__ float wredsum(float v) {
#pragma unroll
    for (int o = 16; o; o >>= 1) v += __shfl_xor_sync(0xffffffffu, v, o);
    return v;
}

__device__ __forceinline__ float blockSum(float v) {
    __shared__ float red[32];
    int lane = threadIdx.x & 31, w = threadIdx.x >> 5;
    int nw = (blockDim.x + 31) >> 5;
    v = wredsum(v);
    if (lane == 0) red[w] = v;
    __syncthreads();
    if (threadIdx.x == 0) {
        float s = 0.f;
        for (int i = 0; i < nw; i++) s += red[i];
        red[0] = s;
    }
    __syncthreads();
    float r = red[0];
    __syncthreads();
    return r;
}

__device__ __forceinline__ float blockMax(float v) {
    __shared__ float red[32];
    int lane = threadIdx.x & 31, w = threadIdx.x >> 5;
    int nw = (blockDim.x + 31) >> 5;
#pragma unroll
    for (int o = 16; o; o >>= 1) v = fmaxf(v, __shfl_xor_sync(0xffffffffu, v, o));
    if (lane == 0) red[w] = v;
    __syncthreads();
    if (threadIdx.x == 0) {
        float s = -3.4e38f;
        for (int i = 0; i < nw; i++) s = fmaxf(s, red[i]);
        red[0] = s;
    }
    __syncthreads();
    float r = red[0];
    __syncthreads();
    return r;
}

__device__ __forceinline__ unsigned long long ffma2(unsigned long long a,
                                                    unsigned long long b,
                                                    unsigned long long c) {
    unsigned long long d;
    asm("fma.rn.f32x2 %0, %1, %2, %3;" : "=l"(d) : "l"(a), "l"(b), "l"(c));
    return d;
}
__device__ __forceinline__ unsigned long long pk2(float x, float y) {
    unsigned long long u;
    asm("mov.b64 %0, {%1,%2};" : "=l"(u) : "f"(x), "f"(y));
    return u;
}
__device__ __forceinline__ float2 upk2(unsigned long long u) {
    float2 f;
    asm("mov.b64 {%0,%1}, %2;" : "=f"(f.x), "=f"(f.y) : "l"(u));
    return f;
}
__device__ __forceinline__ float dot4(float4 a, float4 b) {
    return a.x * b.x + a.y * b.y + a.z * b.z + a.w * b.w;
}
__device__ __forceinline__ float sigf(float x) { return 1.f / (1.f + expf(-x)); }

// ============ K_P1: blocks 0-127 att | 128-383 gates_early | 384-391 zero ======
__global__ void k_p1(const float* __restrict__ x, const float* __restrict__ h0,
                     const float* __restrict__ attn_W, const float* __restrict__ attn_b,
                     const float* __restrict__ W_ih, const float* __restrict__ W_hh,
                     float* __restrict__ out) {
    int b = blockIdx.x;
    if (b >= 384) {
        int i = (b - 384) * 256 + threadIdx.x;  // 0..2047
        g_ctx[i] = 0.f;
        g_sel0[i] = 0.f;
        out[Vv + i] = 0.f;
        return;
    }
    __shared__ float z[TWO_H];  // [xe | h0]
    int t = threadIdx.x, lane = t & 31, warp = t >> 5;
    for (int i = t; i < Hd; i += 256) { z[i] = x[i]; z[Hd + i] = h0[i]; }
    __syncthreads();
    const float4* Z = (const float4*)z;

    if (b < 128) {  // att logits
        int r0 = b * 16 + warp * 2, r1 = r0 + 1;
        const float4* W0 = (const float4*)(attn_W + (size_t)r0 * TWO_H);
        const float4* W1 = (const float4*)(attn_W + (size_t)r1 * TWO_H);
        float s0 = 0.f, s1 = 0.f;
#pragma unroll
        for (int half = 0; half < 2; half++) {
            float4 a[8], bb[8];
#pragma unroll
            for (int j = 0; j < 8; j++) a[j] = W0[lane + (half * 8 + j) * 32];
#pragma unroll
            for (int j = 0; j < 8; j++) bb[j] = W1[lane + (half * 8 + j) * 32];
#pragma unroll
            for (int j = 0; j < 8; j++) {
                float4 zz = Z[lane + (half * 8 + j) * 32];
                s0 += dot4(a[j], zz);
                s1 += dot4(bb[j], zz);
            }
        }
        s0 = wredsum(s0);
        s1 = wredsum(s1);
        if (lane == 0) {
            g_att[r0] = s0 + attn_b[r0];
            g_att[r1] = s1 + attn_b[r1];
        }
    } else {  // gates_early: W_ih[:,0:1024].xe + W_hh.h0
        int r0 = (b - 128) * 16 + warp * 2, r1 = r0 + 1;
        const float4* Wx0 = (const float4*)(W_ih + (size_t)r0 * (3 * Hd));
        const float4* Wx1 = (const float4*)(W_ih + (size_t)r1 * (3 * Hd));
        const float4* Wh0 = (const float4*)(W_hh + (size_t)r0 * Hd);
        const float4* Wh1 = (const float4*)(W_hh + (size_t)r1 * Hd);
        float s0 = 0.f, s1 = 0.f;
        {
            float4 a[8], bb[8];
#pragma unroll
            for (int j = 0; j < 8; j++) a[j] = Wx0[lane + j * 32];
#pragma unroll
            for (int j = 0; j < 8; j++) bb[j] = Wx1[lane + j * 32];
#pragma unroll
            for (int j = 0; j < 8; j++) {
                float4 zz = Z[lane + j * 32];
                s0 += dot4(a[j], zz);
                s1 += dot4(bb[j], zz);
            }
        }
        {
            float4 a[8], bb[8];
#pragma unroll
            for (int j = 0; j < 8; j++) a[j] = Wh0[lane + j * 32];
#pragma unroll
            for (int j = 0; j < 8; j++) bb[j] = Wh1[lane + j * 32];
#pragma unroll
            for (int j = 0; j < 8; j++) {
                float4 zz = Z[256 + lane + j * 32];
                s0 += dot4(a[j], zz);
                s1 += dot4(bb[j], zz);
            }
        }
        s0 = wredsum(s0);
        s1 = wredsum(s1);
        if (lane == 0) { g_gates[r0] = s0; g_gates[r1] = s1; }
    }
}

// ---------------- K2: softmax(att), rho, copy xe ----------------
__global__ void k_soft_rho(const int* __restrict__ sentence,
                           const float* __restrict__ prev_probs,
                           const int* __restrict__ prev_word,
                           const float* __restrict__ x) {
    int t = threadIdx.x;  // 1024
    g_lstm_in[t] = x[t];
    float a0 = g_att[t], a1 = g_att[t + 1024];
    float M = blockMax(fmaxf(a0, a1));
    float e0 = expf(a0 - M), e1 = expf(a1 - M);
    float Ssum = blockSum(e0 + e1);
    float inv = 1.f / Ssum;
    g_attnw[t] = e0 * inv;
    g_attnw[t + 1024] = e1 * inv;

    int pw = prev_word[0];
    float r0 = (sentence[t] == pw) ? prev_probs[Vv + t] : 0.f;
    float r1 = (sentence[t + 1024] == pw) ? prev_probs[Vv + t + 1024] : 0.f;
    float Rs = blockSum(r0 + r1);
    float rin = 1.f / (Rs + 1e-9f);
    g_rho[t] = r0 * rin;
    g_rho[t + 1024] = r1 * rin;
}

// ---------------- K3: ctx / sel0 ----------------
__global__ void k_ctx(const float* __restrict__ enc) {
    __shared__ float aw[64], rh[64];
    int t = threadIdx.x;
    int cb = blockIdx.x & 7;
    int sc = blockIdx.x >> 3;
    int col = cb * 256 + t;
    int s0 = sc * 64;
    if (t < 64) { aw[t] = g_attnw[s0 + t]; rh[t] = g_rho[s0 + t]; }
    __syncthreads();
    float ac = 0.f, as = 0.f;
#pragma unroll 16
    for (int i = 0; i < 64; i++) {
        float e = enc[(size_t)(s0 + i) * TWO_H + col];
        ac += aw[i] * e;
        as += rh[i] * e;
    }
    atomicAdd(&g_ctx[col], ac);
    atomicAdd(&g_sel0[col], as);
}

// ---------------- K4: projections ----------------
__global__ void k_proj(const float* __restrict__ comb_W, const float* __restrict__ comb_b,
                       const float* __restrict__ Ws_W, const float* __restrict__ Ws_b) {
    __shared__ float z[TWO_H];
    int t = threadIdx.x, lane = t & 31, warp = t >> 5;
    bool sel = blockIdx.x < 64;
    const float* src = sel ? g_sel0 : g_ctx;
    for (int i = t; i < TWO_H; i += 256) z[i] = src[i];
    __syncthreads();
    int r0 = (blockIdx.x & 63) * 16 + warp * 2, r1 = r0 + 1;
    const float* W = sel ? Ws_W : comb_W;
    const float4* W0 = (const float4*)(W + (size_t)r0 * TWO_H);
    const float4* W1 = (const float4*)(W + (size_t)r1 * TWO_H);
    const float4* Z = (const float4*)z;
    float s0 = 0.f, s1 = 0.f;
#pragma unroll
    for (int half = 0; half < 2; half++) {
        float4 a[8], b[8];
#pragma unroll
        for (int j = 0; j < 8; j++) a[j] = W0[lane + (half * 8 + j) * 32];
#pragma unroll
        for (int j = 0; j < 8; j++) b[j] = W1[lane + (half * 8 + j) * 32];
#pragma unroll
        for (int j = 0; j < 8; j++) {
            float4 zz = Z[lane + (half * 8 + j) * 32];
            s0 += dot4(a[j], zz);
            s1 += dot4(b[j], zz);
        }
    }
    s0 = wredsum(s0);
    s1 = wredsum(s1);
    if (lane == 0) {
        if (sel) { g_lstm_in[Hd + r0] = s0 + Ws_b[r0]; g_lstm_in[Hd + r1] = s1 + Ws_b[r1]; }
        else     { g_lstm_in[2 * Hd + r0] = s0 + comb_b[r0]; g_lstm_in[2 * Hd + r1] = s1 + comb_b[r1]; }
    }
}

// ---------------- K5: gates_late: += W_ih[:,1024:3072] . lstm_in[1024:3072] ----
__global__ void k_gates2(const float* __restrict__ W_ih) {
    __shared__ float z[TWO_H];
    int t = threadIdx.x, lane = t & 31, warp = t >> 5;
    for (int i = t; i < TWO_H; i += 256) z[i] = g_lstm_in[Hd + i];
    __syncthreads();
    int r0 = blockIdx.x * 16 + warp * 2, r1 = r0 + 1;
    const float4* W0 = (const float4*)(W_ih + (size_t)r0 * (3 * Hd) + Hd);
    const float4* W1 = (const float4*)(W_ih + (size_t)r1 * (3 * Hd) + Hd);
    const float4* Z = (const float4*)z;
    float s0 = 0.f, s1 = 0.f;
#pragma unroll
    for (int half = 0; half < 2; half++) {
        float4 a[8], b[8];
#pragma unroll
        for (int j = 0; j < 8; j++) a[j] = W0[lane + (half * 8 + j) * 32];
#pragma unroll
        for (int j = 0; j < 8; j++) b[j] = W1[lane + (half * 8 + j) * 32];
#pragma unroll
        for (int j = 0; j < 8; j++) {
            float4 zz = Z[lane + (half * 8 + j) * 32];
            s0 += dot4(a[j], zz);
            s1 += dot4(b[j], zz);
        }
    }
    s0 = wredsum(s0);
    s1 = wredsum(s1);
    if (lane == 0) {
        g_gates[r0] += s0;
        g_gates[r1] += s1;
    }
}

// ---------------- K6: LSTM cell ----------------
__global__ void k_cell(const float* __restrict__ b_ih, const float* __restrict__ b_hh,
                       const float* __restrict__ c0, float* __restrict__ out) {
    int k = blockIdx.x * 256 + threadIdx.x;
    float iv = g_gates[k]          + b_ih[k]          + b_hh[k];
    float fv = g_gates[k + Hd]     + b_ih[k + Hd]     + b_hh[k + Hd];
    float gv = g_gates[k + 2 * Hd] + b_ih[k + 2 * Hd] + b_hh[k + 2 * Hd];
    float ov = g_gates[k + 3 * Hd] + b_ih[k + 3 * Hd] + b_hh[k + 3 * Hd];
    float c1 = sigf(fv) * c0[k] + sigf(iv) * tanhf(gv);
    float h1 = sigf(ov) * tanhf(c1);
    g_h1[k] = h1;
    out[POS_H1 + k] = h1;
    out[POS_C1 + k] = c1;
}

// ---------------- K_BIG: scorec (blocks 0..127, FFMA2) + scoreg (128+) --------
// NOTE: no minBlocksPerMultiprocessor clamp — round-4 regression was register
// spills from the 128-reg cap (c[8][4]=64 regs + prefetch). Full 255-reg budget.
#define SC_NBLK 128
#define OFF_HS  0
#define OFF_BS  512
#define OFF_A2  1024
#define A2_LD   130
#define OFF_B   34304
#define B_LD    132
#define SMEM_BIG 51200

__global__ void __launch_bounds__(256) k_big(
    const float* __restrict__ enc, const float* __restrict__ Wc_W,
    const float* __restrict__ Wc_b, const float* __restrict__ Wo_W,
    const float* __restrict__ Wo_b, float* __restrict__ out) {
    extern __shared__ char smem[];
    int t = threadIdx.x, lane = t & 31, wid = t >> 5;

    if (blockIdx.x >= SC_NBLK) {
        // ===== scoreg: out[r] = Wo_W[r,:] . h1 + Wo_b[r] =====
        int warpg = (blockIdx.x - SC_NBLK) * 8 + wid;
        int r0 = warpg * 2, r1 = r0 + 1;
        if (r0 >= Vv) return;
        float4 hf[8];
        const float4* H4 = (const float4*)g_h1;
#pragma unroll
        for (int j = 0; j < 8; j++) hf[j] = H4[lane + j * 32];
        const float4* W0 = (const float4*)(Wo_W + (size_t)r0 * Hd);
        const float4* W1 = (const float4*)(Wo_W + (size_t)r1 * Hd);
        bool has1 = (r1 < Vv);
        float4 a[8], b[8];
#pragma unroll
        for (int j = 0; j < 8; j++) a[j] = W0[lane + j * 32];
        if (has1) {
#pragma unroll
            for (int j = 0; j < 8; j++) b[j] = W1[lane + j * 32];
        }
        float s0 = 0.f, s1 = 0.f;
#pragma unroll
        for (int j = 0; j < 8; j++) s0 += dot4(a[j], hf[j]);
        if (has1) {
#pragma unroll
            for (int j = 0; j < 8; j++) s1 += dot4(b[j], hf[j]);
        }
        s0 = wredsum(s0);
        s1 = wredsum(s1);
        if (lane == 0) {
            out[r0] = s0 + Wo_b[r0];
            if (has1) out[r1] = s1 + Wo_b[r1];
        }
        return;
    }

    // ===== scorec: 128x128 tile of M = enc @ Wc^T; out += tanh(M+b) . h1 =====
    float* hs = (float*)(smem + OFF_HS);
    float* bs = (float*)(smem + OFF_BS);
    unsigned long long* As2 = (unsigned long long*)(smem + OFF_A2);
    float* Bs = (float*)(smem + OFF_B);

    int s0 = (blockIdx.x & 15) * 128;   // 16 s-blocks
    int j0 = (blockIdx.x >> 4) * 128;   // 8 j-blocks
    int tx = t & 15, ty = t >> 4;
    int m0 = ty * 8, jj0 = tx * 8;

    if (t < 128) { hs[t] = g_h1[j0 + t]; bs[t] = Wc_b[j0 + t]; }

    const float4* A4 = (const float4*)enc;   // row stride 512 float4
    const float4* B4 = (const float4*)Wc_W;

    // prefetch chunk 0
    float4 ra[4], rb[4];
#pragma unroll
    for (int p = 0; p < 4; p++) {
        int f = t + p * 256;
        int row = f >> 3, kq = f & 7;   // row 0..127, kq 0..7
        ra[p] = A4[(size_t)(s0 + row) * 512 + kq];
        rb[p] = B4[(size_t)(j0 + row) * 512 + kq];
    }

    unsigned long long c[8][4] = {};
    for (int ch = 0; ch < 64; ch++) {   // K chunks of 32
        __syncthreads();
        // store chunk ch (transposed, A duplicated to f32x2)
#pragma unroll
        for (int p = 0; p < 4; p++) {
            int f = t + p * 256;
            int row = f >> 3, kq = f & 7;
            float4 va = ra[p], vb = rb[p];
            As2[(kq * 4 + 0) * A2_LD + row] = pk2(va.x, va.x);
            As2[(kq * 4 + 1) * A2_LD + row] = pk2(va.y, va.y);
            As2[(kq * 4 + 2) * A2_LD + row] = pk2(va.z, va.z);
            As2[(kq * 4 + 3) * A2_LD + row] = pk2(va.w, va.w);
            Bs[(kq * 4 + 0) * B_LD + row] = vb.x;
            Bs[(kq * 4 + 1) * B_LD + row] = vb.y;
            Bs[(kq * 4 + 2) * B_LD + row] = vb.z;
            Bs[(kq * 4 + 3) * B_LD + row] = vb.w;
        }
        // prefetch next chunk (overlaps with compute)
        if (ch < 63) {
            int kb = (ch + 1) * 8;
#pragma unroll
            for (int p = 0; p < 4; p++) {
                int f = t + p * 256;
                int row = f >> 3, kq = f & 7;
                ra[p] = A4[(size_t)(s0 + row) * 512 + kb + kq];
                rb[p] = B4[(size_t)(j0 + row) * 512 + kb + kq];
            }
        }
        __syncthreads();
#pragma unroll
        for (int kk = 0; kk < 32; kk++) {
            const ulonglong2* Ar = (const ulonglong2*)&As2[kk * A2_LD + m0];
            ulonglong2 a01 = Ar[0], a23 = Ar[1], a45 = Ar[2], a67 = Ar[3];
            const ulonglong2* Br = (const ulonglong2*)&Bs[kk * B_LD + jj0];
            ulonglong2 b01 = Br[0], b23 = Br[1];
            c[0][0] = ffma2(a01.x, b01.x, c[0][0]); c[0][1] = ffma2(a01.x, b01.y, c[0][1]);
            c[0][2] = ffma2(a01.x, b23.x, c[0][2]); c[0][3] = ffma2(a01.x, b23.y, c[0][3]);
            c[1][0] = ffma2(a01.y, b01.x, c[1][0]); c[1][1] = ffma2(a01.y, b01.y, c[1][1]);
            c[1][2] = ffma2(a01.y, b23.x, c[1][2]); c[1][3] = ffma2(a01.y, b23.y, c[1][3]);
            c[2][0] = ffma2(a23.x, b01.x, c[2][0]); c[2][1] = ffma2(a23.x, b01.y, c[2][1]);
            c[2][2] = ffma2(a23.x, b23.x, c[2][2]); c[2][3] = ffma2(a23.x, b23.y, c[2][3]);
            c[3][0] = ffma2(a23.y, b01.x, c[3][0]); c[3][1] = ffma2(a23.y, b01.y, c[3][1]);
            c[3][2] = ffma2(a23.y, b23.x, c[3][2]); c[3][3] = ffma2(a23.y, b23.y, c[3][3]);
            c[4][0] = ffma2(a45.x, b01.x, c[4][0]); c[4][1] = ffma2(a45.x, b01.y, c[4][1]);
            c[4][2] = ffma2(a45.x, b23.x, c[4][2]); c[4][3] = ffma2(a45.x, b23.y, c[4][3]);
            c[5][0] = ffma2(a45.y, b01.x, c[5][0]); c[5][1] = ffma2(a45.y, b01.y, c[5][1]);
            c[5][2] = ffma2(a45.y, b23.x, c[5][2]); c[5][3] = ffma2(a45.y, b23.y, c[5][3]);
            c[6][0] = ffma2(a67.x, b01.x, c[6][0]); c[6][1] = ffma2(a67.x, b01.y, c[6][1]);
            c[6][2] = ffma2(a67.x, b23.x, c[6][2]); c[6][3] = ffma2(a67.x, b23.y, c[6][3]);
            c[7][0] = ffma2(a67.y, b01.x, c[7][0]); c[7][1] = ffma2(a67.y, b01.y, c[7][1]);
            c[7][2] = ffma2(a67.y, b23.x, c[7][2]); c[7][3] = ffma2(a67.y, b23.y, c[7][3]);
        }
    }

    // epilogue: part[m] = sum_j tanh(c + bs[j]) * hs[j]; reduce over tx (16 lanes)
#pragma unroll
    for (int m = 0; m < 8; m++) {
        float part = 0.f;
#pragma unroll
        for (int jp = 0; jp < 4; jp++) {
            float2 f = upk2(c[m][jp]);
            int j = jj0 + jp * 2;
            part += tanhf(f.x + bs[j]) * hs[j];
            part += tanhf(f.y + bs[j + 1]) * hs[j + 1];
        }
#pragma unroll
        for (int o = 8; o; o >>= 1) part += __shfl_xor_sync(0xffffffffu, part, o);
        if ((lane & 15) == 0) atomicAdd(&out[Vv + s0 + m0 + m], part);
    }
}

// ---------------- final softmax over out[0:VS) ----------------
__global__ void k_pmax(const float* __restrict__ out) {
    float m = -3.4e38f;
    for (int i = blockIdx.x * 256 + threadIdx.x; i < VS; i += 64 * 256)
        m = fmaxf(m, out[i]);
    m = blockMax(m);
    if (threadIdx.x == 0) g_pmax[blockIdx.x] = m;
}

__global__ void k_expsum(float* __restrict__ out) {
    float m = -3.4e38f;
    for (int i = threadIdx.x; i < 64; i += 256) m = fmaxf(m, g_pmax[i]);
    float M = blockMax(m);
    float s = 0.f;
    for (int i = blockIdx.x * 256 + threadIdx.x; i < VS; i += 64 * 256) {
        float e = expf(out[i] - M);
        out[i] = e;
        s += e;
    }
    s = blockSum(s);
    if (threadIdx.x == 0) g_psum[blockIdx.x] = s;
}

__global__ void k_norm(float* __restrict__ out) {
    float s = 0.f;
    for (int i = threadIdx.x; i < 64; i += 256) s += g_psum[i];
    float tot = blockSum(s);
    float inv = 1.f / tot;
    for (int i = blockIdx.x * 256 + threadIdx.x; i < VS; i += 64 * 256)
        out[i] *= inv;
}

// ---------------- launch ----------------
extern "C" void kernel_launch(void* const* d_in, const int* in_sizes, int n_in,
                              void* d_out, int out_size) {
    const float* x          = (const float*)d_in[0];
    const float* enc        = (const float*)d_in[1];
    const int*   sentence   = (const int*)d_in[2];
    const float* prev_probs = (const float*)d_in[3];
    const float* h0         = (const float*)d_in[4];
    const float* c0         = (const float*)d_in[5];
    const float* attn_W     = (const float*)d_in[6];
    const float* attn_b     = (const float*)d_in[7];
    const float* comb_W     = (const float*)d_in[8];
    const float* comb_b     = (const float*)d_in[9];
    const float* Ws_W       = (const float*)d_in[10];
    const float* Ws_b       = (const float*)d_in[11];
    const float* Wo_W       = (const float*)d_in[12];
    const float* Wo_b       = (const float*)d_in[13];
    const float* Wc_W       = (const float*)d_in[14];
    const float* Wc_b       = (const float*)d_in[15];
    const float* W_ih       = (const float*)d_in[16];
    const float* W_hh       = (const float*)d_in[17];
    const float* b_ih       = (const float*)d_in[18];
    const float* b_hh       = (const float*)d_in[19];
    const int*   prev_word  = (const int*)d_in[20];
    float* out = (float*)d_out;

    cudaFuncSetAttribute(k_big, cudaFuncAttributeMaxDynamicSharedMemorySize, SMEM_BIG);

    k_p1<<<392, 256>>>(x, h0, attn_W, attn_b, W_ih, W_hh, out);
    k_soft_rho<<<1, 1024>>>(sentence, prev_probs, prev_word, x);
    k_ctx<<<256, 256>>>(enc);
    k_proj<<<128, 256>>>(comb_W, comb_b, Ws_W, Ws_b);
    k_gates2<<<256, 256>>>(W_ih);
    k_cell<<<4, 256>>>(b_ih, b_hh, c0, out);
    k_big<<<SC_NBLK + 3142, 256, SMEM_BIG>>>(enc, Wc_W, Wc_b, Wo_W, Wo_b, out);
    k_pmax<<<64, 256>>>(out);
    k_expsum<<<64, 256>>>(out);
    k_norm<<<64, 256>>>(out);
}